// round 4
// baseline (speedup 1.0000x reference)
#include <cuda_runtime.h>

// FeedForwardQuantum — persistent single-wave streaming kernel.
//   theta = dot(x_row, W1) + b1 ; out = cos(theta)*cos(phi) * W2 + b2
// EMBED_DIM = 1024 (256 float4), tokens = 32768.
//
// Grid = 512 CTAs (single wave on 148-152 SMs), 8 warps/CTA, each warp owns
// 8 contiguous tokens. W1/W2/b2 staged in smem once per CTA (keeps the
// L1tex global queue pure x/out streaming). Software-pipelined: next token's
// x loads are issued right after the current xv registers are consumed, so
// the shuffle-reduce + stores hide under DRAM latency.

#define EMBED_F4        256
#define WARPS_PER_CTA     8
#define THREADS         (WARPS_PER_CTA * 32)
#define TOKENS_PER_WARP   8

__global__ __launch_bounds__(THREADS, 4)
void ffq_kernel(const float4* __restrict__ x,
                const float4* __restrict__ W1,
                const float*  __restrict__ b1,
                const float*  __restrict__ phi,
                const float4* __restrict__ W2,
                const float4* __restrict__ b2,
                float4* __restrict__ out)
{
    __shared__ float4 sW1[EMBED_F4];
    __shared__ float4 sW2[EMBED_F4];
    __shared__ float4 sB2[EMBED_F4];

    const int tid = threadIdx.x;
    // 256 threads, 256 float4 each — one element per thread.
    sW1[tid] = W1[tid];
    sW2[tid] = W2[tid];
    sB2[tid] = b2[tid];
    __syncthreads();

    const int warp = tid >> 5;
    const int lane = tid & 31;
    const float cphi = __cosf(phi[0]);
    const float bias1 = b1[0];

    const long warpId = (long)blockIdx.x * WARPS_PER_CTA + warp;
    const long tok0   = warpId * TOKENS_PER_WARP;
    const float4* __restrict__ xp = x   + tok0 * EMBED_F4 + lane;
    float4*       __restrict__ op = out + tok0 * EMBED_F4 + lane;

    // Prologue: front-batch token 0's loads.
    float4 xv[8];
    #pragma unroll
    for (int i = 0; i < 8; i++)
        xv[i] = __ldcs(xp + 32 * i);

    #pragma unroll
    for (int t = 0; t < TOKENS_PER_WARP; t++) {
        // Consume xv into the partial dot (frees xv registers).
        float p = 0.0f;
        #pragma unroll
        for (int i = 0; i < 8; i++) {
            const float4 wv = sW1[lane + 32 * i];
            p = fmaf(xv[i].x, wv.x,
                fmaf(xv[i].y, wv.y,
                fmaf(xv[i].z, wv.z,
                fmaf(xv[i].w, wv.w, p))));
        }

        // Issue next token's loads NOW — reduction + stores hide under them.
        if (t + 1 < TOKENS_PER_WARP) {
            #pragma unroll
            for (int i = 0; i < 8; i++)
                xv[i] = __ldcs(xp + (long)(t + 1) * EMBED_F4 + 32 * i);
        }

        // Warp-only reduction.
        #pragma unroll
        for (int o = 16; o > 0; o >>= 1)
            p += __shfl_xor_sync(0xffffffffu, p, o);

        const float q = __cosf(p + bias1) * cphi;

        // Streaming stores of q * W2 + b2.
        #pragma unroll
        for (int i = 0; i < 8; i++) {
            const float4 w2 = sW2[lane + 32 * i];
            const float4 bb = sB2[lane + 32 * i];
            float4 o4;
            o4.x = fmaf(q, w2.x, bb.x);
            o4.y = fmaf(q, w2.y, bb.y);
            o4.z = fmaf(q, w2.z, bb.z);
            o4.w = fmaf(q, w2.w, bb.w);
            __stcs(op + (long)t * EMBED_F4 + 32 * i, o4);
        }
    }
}

extern "C" void kernel_launch(void* const* d_in, const int* in_sizes, int n_in,
                              void* d_out, int out_size)
{
    const float4* x   = (const float4*)d_in[0];
    const float4* W1  = (const float4*)d_in[1];
    const float*  b1  = (const float*) d_in[2];
    const float*  phi = (const float*) d_in[3];
    const float4* W2  = (const float4*)d_in[4];
    const float4* b2  = (const float4*)d_in[5];
    float4* out = (float4*)d_out;

    const int tokens = in_sizes[0] / (EMBED_F4 * 4);              // 32768
    const int ctas   = tokens / (WARPS_PER_CTA * TOKENS_PER_WARP); // 512
    ffq_kernel<<<ctas, THREADS>>>(x, W1, b1, phi, W2, b2, out);
}

// round 6
// speedup vs baseline: 2.5555x; 2.5555x over previous
#include <cuda_runtime.h>

// FeedForwardQuantum — warp-per-token, full-occupancy variant.
//   theta = dot(x_row, W1) + b1 ; out = cos(theta)*cos(phi) * W2 + b2
// EMBED_DIM=1024 (256 float4), tokens = 32768.
//
// vs R2 (40.7us kernel): x loads split into 2 batches of 4 float4 so the
// register footprint fits <=32 regs (__launch_bounds__(256,8)) -> 8 CTAs/SM,
// 64 warps/SM. Latency hiding here comes from warp count (SM-level), not
// intra-warp MLP: 64 warps x 512B = 32KB in flight per SM, 2x the HBM
// BW*latency product. Shuffle-only reduction, no smem, no block barrier.

#define EMBED_F4       256   // float4s per token row
#define WARPS_PER_CTA    8
#define THREADS        (WARPS_PER_CTA * 32)

__global__ __launch_bounds__(THREADS, 8)
void ffq_kernel(const float4* __restrict__ x,
                const float4* __restrict__ W1,
                const float*  __restrict__ b1,
                const float*  __restrict__ phi,
                const float4* __restrict__ W2,
                const float4* __restrict__ b2,
                float4* __restrict__ out)
{
    const int warp = threadIdx.x >> 5;
    const int lane = threadIdx.x & 31;
    const long token = (long)blockIdx.x * WARPS_PER_CTA + warp;
    const long rbase = token * EMBED_F4 + lane;

    float p = 0.0f;

    // Batch 1: 4 front-batched streaming loads, then consume.
    {
        float4 xv[4];
        #pragma unroll
        for (int i = 0; i < 4; i++)
            xv[i] = __ldcs(&x[rbase + 32 * i]);
        #pragma unroll
        for (int i = 0; i < 4; i++) {
            const float4 wv = W1[lane + 32 * i];   // 4KiB, L1-resident
            p = fmaf(xv[i].x, wv.x,
                fmaf(xv[i].y, wv.y,
                fmaf(xv[i].z, wv.z,
                fmaf(xv[i].w, wv.w, p))));
        }
    }
    // Batch 2.
    {
        float4 xv[4];
        #pragma unroll
        for (int i = 0; i < 4; i++)
            xv[i] = __ldcs(&x[rbase + 32 * (i + 4)]);
        #pragma unroll
        for (int i = 0; i < 4; i++) {
            const float4 wv = W1[lane + 32 * (i + 4)];
            p = fmaf(xv[i].x, wv.x,
                fmaf(xv[i].y, wv.y,
                fmaf(xv[i].z, wv.z,
                fmaf(xv[i].w, wv.w, p))));
        }
    }

    // Warp-only reduction: no smem, no block barrier.
    #pragma unroll
    for (int o = 16; o > 0; o >>= 1)
        p += __shfl_xor_sync(0xffffffffu, p, o);

    const float q = __cosf(p + b1[0]) * __cosf(phi[0]);

    // out = q * W2 + b2  (W2/b2 L1-resident), streaming stores.
    #pragma unroll
    for (int i = 0; i < 8; i++) {
        const float4 w2 = W2[lane + 32 * i];
        const float4 bb = b2[lane + 32 * i];
        float4 o;
        o.x = fmaf(q, w2.x, bb.x);
        o.y = fmaf(q, w2.y, bb.y);
        o.z = fmaf(q, w2.z, bb.z);
        o.w = fmaf(q, w2.w, bb.w);
        __stcs(&out[rbase + 32 * i], o);
    }
}

extern "C" void kernel_launch(void* const* d_in, const int* in_sizes, int n_in,
                              void* d_out, int out_size)
{
    const float4* x   = (const float4*)d_in[0];
    const float4* W1  = (const float4*)d_in[1];
    const float*  b1  = (const float*) d_in[2];
    const float*  phi = (const float*) d_in[3];
    const float4* W2  = (const float4*)d_in[4];
    const float4* b2  = (const float4*)d_in[5];
    float4* out = (float4*)d_out;

    const int tokens = in_sizes[0] / (EMBED_F4 * 4);   // 32768
    ffq_kernel<<<tokens / WARPS_PER_CTA, THREADS>>>(x, W1, b1, phi, W2, b2, out);
}